// round 3
// baseline (speedup 1.0000x reference)
#include <cuda_runtime.h>
#include <math.h>

#define NN 100000
#define NE 640000
#define IND 64
#define HH  128
#define NG  128

// ---------------- scratch (static device globals; no runtime alloc) ----------------
__device__ float g_h [NN*HH];
__device__ float g_m [NN*HH];
__device__ float g_fb[NN*HH];
__device__ float g_gb[NN*HH];
__device__ float g_Wint[IND*HH];
__device__ float g_Wft[HH*HH];
__device__ float g_Uft[HH*HH];
__device__ float g_Wht[HH*HH];
__device__ float g_Uht[HH*HH];
__device__ float g_e  [NN];
__device__ int   g_bounds[NG+1];
__device__ float g_hl[NG*HH];
__device__ float g_cl[NG*HH];
__device__ float g_qs[NG*2*HH];

__device__ __forceinline__ float sigf(float z)   { return __fdividef(1.f, 1.f + __expf(-z)); }
__device__ __forceinline__ float tanhfast(float z){ return 1.f - __fdividef(2.f, __expf(2.f*z) + 1.f); }

// ---------------- transpose: src[R][C] -> dst[C][R] ----------------
__global__ void k_transpose(const float* __restrict__ src, float* __restrict__ dst, int R, int C){
    __shared__ float t[32][33];
    int c = blockIdx.x*32 + threadIdx.x;
    int r = blockIdx.y*32 + threadIdx.y;
    if (r < R && c < C) t[threadIdx.y][threadIdx.x] = src[r*C + c];
    __syncthreads();
    int rc = blockIdx.x*32 + threadIdx.y;   // dst row (src col)
    int cc = blockIdx.y*32 + threadIdx.x;   // dst col (src row)
    if (rc < C && cc < R) dst[rc*R + cc] = t[threadIdx.x][threadIdx.y];
}

// ---------------- segment boundaries from sorted batch ----------------
__global__ void k_bounds(const int* __restrict__ batch){
    int i = blockIdx.x*blockDim.x + threadIdx.x;
    if (i >= NN) return;
    int b = batch[i];
    if (i == 0)      { for (int g = 0;    g <= b;  g++) g_bounds[g] = 0; }
    else             { int pb = batch[i-1];
                       for (int g = pb+1; g <= b;  g++) g_bounds[g] = i; }
    if (i == NN-1)   { for (int g = b+1;  g <= NG; g++) g_bounds[g] = NN; }
}

// ---------------- zero helpers ----------------
__global__ void k_zero4(float4* __restrict__ p, int n4){
    int i = blockIdx.x*blockDim.x + threadIdx.x;
    if (i < n4) p[i] = make_float4(0.f,0.f,0.f,0.f);
}
__global__ void k_zero_s2s(){
    int i = blockIdx.x*blockDim.x + threadIdx.x;
    if (i < NG*HH) { g_hl[i] = 0.f; g_cl[i] = 0.f; }
    if (i < NG*2*HH) g_qs[i] = 0.f;
}

// ---------------- input layer: h = relu(x @ W_in^T + b_in) ----------------
// grid: (NN+63)/64 blocks, 256 threads; smem: Wt_in[64][128] + x tile[64][64] = 48KB
__global__ __launch_bounds__(256) void k_input(const float* __restrict__ x,
                                               const float* __restrict__ bin){
    extern __shared__ float sm[];
    float4* Ws4 = (float4*)sm;                 // 2048 f4
    float4* Xs4 = (float4*)(sm + IND*HH);      // 1024 f4
    int tid = threadIdx.x;
    int jt = tid & 31, nt = tid >> 5;

    const float4* Wg = (const float4*)g_Wint;
#pragma unroll
    for (int i = 0; i < 8; i++) Ws4[tid + i*256] = Wg[tid + i*256];

    int base = blockIdx.x * 64;
    const float4* Xg = (const float4*)x;
#pragma unroll
    for (int i = 0; i < 4; i++){
        int q = tid + i*256;
        int rn = q >> 4, col = q & 15;         // 16 f4 per 64-float row
        int gn = base + rn;
        Xs4[q] = (gn < NN) ? Xg[gn*16 + col] : make_float4(0.f,0.f,0.f,0.f);
    }
    __syncthreads();

    float acc[8][4];
#pragma unroll
    for (int i = 0; i < 8; i++){ acc[i][0]=0.f; acc[i][1]=0.f; acc[i][2]=0.f; acc[i][3]=0.f; }

    for (int k = 0; k < IND; k += 4){
        float a[8][4];
#pragma unroll
        for (int i = 0; i < 8; i++){
            float4 t4 = Xs4[(nt*8+i)*16 + (k>>2)];
            a[i][0]=t4.x; a[i][1]=t4.y; a[i][2]=t4.z; a[i][3]=t4.w;
        }
#pragma unroll
        for (int kk = 0; kk < 4; kk++){
            float4 w = Ws4[(k+kk)*32 + jt];
#pragma unroll
            for (int i = 0; i < 8; i++){
                acc[i][0] += a[i][kk]*w.x;
                acc[i][1] += a[i][kk]*w.y;
                acc[i][2] += a[i][kk]*w.z;
                acc[i][3] += a[i][kk]*w.w;
            }
        }
    }
    float4 bb = ((const float4*)bin)[jt];
#pragma unroll
    for (int i = 0; i < 8; i++){
        int n = base + nt*8 + i;
        if (n < NN){
            float4 o;
            o.x = fmaxf(acc[i][0]+bb.x, 0.f);
            o.y = fmaxf(acc[i][1]+bb.y, 0.f);
            o.z = fmaxf(acc[i][2]+bb.z, 0.f);
            o.w = fmaxf(acc[i][3]+bb.w, 0.f);
            ((float4*)g_h)[n*32 + jt] = o;
        }
    }
}

// ---------------- edge scatter: m[dst] += h[src], one warp per edge ----------------
__global__ void k_scatter(const int* __restrict__ src, const int* __restrict__ dst){
    int t = blockIdx.x*blockDim.x + threadIdx.x;
    int e = t >> 5;
    if (e >= NE) return;
    int lane = t & 31;
    int s = __ldg(&src[e]);
    int d = __ldg(&dst[e]);
    float4 v = ((const float4*)g_h)[s*32 + lane];
    float* p = g_m + d*HH + lane*4;
    asm volatile("red.global.add.v4.f32 [%0], {%1, %2, %3, %4};"
                 :: "l"(p), "f"(v.x), "f"(v.y), "f"(v.z), "f"(v.w) : "memory");
}

// ---------------- dual GEMM: z = A@Wt + B@Ut + bias, fused MGU epilogue ----------------
// MODE 0: f = sigmoid(z) -> O1;  g = f * B -> O2
// MODE 1: h_new = (1-Fb)*Hb + Fb*tanh(z) -> Hb (in place)
// persistent grid, 1 block/SM, 192KB dynamic smem
#define SMG ((HH*HH*2 + 64*HH*2) * 4)
template<int MODE>
__global__ __launch_bounds__(256) void k_dualgemm(
    const float* __restrict__ A, const float* __restrict__ B,
    const float* __restrict__ Wt, const float* __restrict__ Ut,
    const float* __restrict__ bias,
    float* __restrict__ O1, float* __restrict__ O2,
    const float* __restrict__ Fb, float* __restrict__ Hb)
{
    extern __shared__ float sm[];
    float4* Ws4 = (float4*)sm;                       // 4096 f4
    float4* Us4 = (float4*)(sm + HH*HH);             // 4096 f4
    float4* As4 = (float4*)(sm + 2*HH*HH);           // 2048 f4
    float4* Bs4 = (float4*)(sm + 2*HH*HH + 64*HH);   // 2048 f4
    int tid = threadIdx.x;
    int jt = tid & 31, nt = tid >> 5;

    const float4* Wg = (const float4*)Wt;
    const float4* Ug = (const float4*)Ut;
#pragma unroll
    for (int i = 0; i < 16; i++){
        Ws4[tid + i*256] = Wg[tid + i*256];
        Us4[tid + i*256] = Ug[tid + i*256];
    }
    float4 bb = ((const float4*)bias)[jt];
    const float4* Ag = (const float4*)A;
    const float4* Bg = (const float4*)B;

    int ntiles = (NN + 63) >> 6;
    for (int tile = blockIdx.x; tile < ntiles; tile += gridDim.x){
        __syncthreads();
        int base = tile << 6;
#pragma unroll
        for (int i = 0; i < 8; i++){
            int q = tid + i*256;
            int rn = q >> 5, col = q & 31;
            int gn = base + rn;
            if (gn < NN){ As4[q] = Ag[gn*32 + col]; Bs4[q] = Bg[gn*32 + col]; }
            else        { float4 z = make_float4(0.f,0.f,0.f,0.f); As4[q] = z; Bs4[q] = z; }
        }
        __syncthreads();

        float acc[8][4];
#pragma unroll
        for (int i = 0; i < 8; i++){ acc[i][0]=0.f; acc[i][1]=0.f; acc[i][2]=0.f; acc[i][3]=0.f; }

        for (int k = 0; k < HH; k += 4){
            float a[8][4], b[8][4];
#pragma unroll
            for (int i = 0; i < 8; i++){
                float4 ta = As4[(nt*8+i)*32 + (k>>2)];
                float4 tb = Bs4[(nt*8+i)*32 + (k>>2)];
                a[i][0]=ta.x; a[i][1]=ta.y; a[i][2]=ta.z; a[i][3]=ta.w;
                b[i][0]=tb.x; b[i][1]=tb.y; b[i][2]=tb.z; b[i][3]=tb.w;
            }
#pragma unroll
            for (int kk = 0; kk < 4; kk++){
                float4 w = Ws4[(k+kk)*32 + jt];
                float4 u = Us4[(k+kk)*32 + jt];
#pragma unroll
                for (int i = 0; i < 8; i++){
                    acc[i][0] += a[i][kk]*w.x + b[i][kk]*u.x;
                    acc[i][1] += a[i][kk]*w.y + b[i][kk]*u.y;
                    acc[i][2] += a[i][kk]*w.z + b[i][kk]*u.z;
                    acc[i][3] += a[i][kk]*w.w + b[i][kk]*u.w;
                }
            }
        }

#pragma unroll
        for (int i = 0; i < 8; i++){
            int n = base + nt*8 + i;
            if (n < NN){
                float z0 = acc[i][0]+bb.x, z1 = acc[i][1]+bb.y;
                float z2 = acc[i][2]+bb.z, z3 = acc[i][3]+bb.w;
                if (MODE == 0){
                    float f0 = sigf(z0), f1 = sigf(z1), f2 = sigf(z2), f3 = sigf(z3);
                    float4 hv = Bs4[(nt*8+i)*32 + jt];   // h[n][j..j+3]
                    float4 o1 = make_float4(f0, f1, f2, f3);
                    float4 o2 = make_float4(f0*hv.x, f1*hv.y, f2*hv.z, f3*hv.w);
                    ((float4*)O1)[n*32 + jt] = o1;
                    ((float4*)O2)[n*32 + jt] = o2;
                } else {
                    float4 fv = ((const float4*)Fb)[n*32 + jt];
                    float4 hv = ((const float4*)Hb)[n*32 + jt];
                    float4 o;
                    o.x = (1.f-fv.x)*hv.x + fv.x*tanhfast(z0);
                    o.y = (1.f-fv.y)*hv.y + fv.y*tanhfast(z1);
                    o.z = (1.f-fv.z)*hv.z + fv.z*tanhfast(z2);
                    o.w = (1.f-fv.w)*hv.w + fv.w*tanhfast(z3);
                    ((float4*)Hb)[n*32 + jt] = o;
                }
            }
        }
    }
}

// ---------------- Set2Set LSTM step (one block per graph) ----------------
__global__ __launch_bounds__(512) void k_lstm(const float* __restrict__ wih,
                                              const float* __restrict__ whh,
                                              const float* __restrict__ bih,
                                              const float* __restrict__ bhh){
    __shared__ float qs[2*HH];
    __shared__ float hs[HH];
    __shared__ float gt[4*HH];
    int g = blockIdx.x, t = threadIdx.x;
    if (t < 2*HH) qs[t] = g_qs[g*2*HH + t];
    if (t < HH)   hs[t] = g_hl[g*HH + t];
    __syncthreads();

    float acc = bih[t] + bhh[t];
    const float4* wr  = (const float4*)(wih + t*2*HH);
    const float4* qs4 = (const float4*)qs;
#pragma unroll 8
    for (int k = 0; k < 64; k++){
        float4 w = wr[k], q = qs4[k];
        acc += w.x*q.x + w.y*q.y + w.z*q.z + w.w*q.w;
    }
    const float4* hr  = (const float4*)(whh + t*HH);
    const float4* hs4 = (const float4*)hs;
#pragma unroll 8
    for (int k = 0; k < 32; k++){
        float4 w = hr[k], q = hs4[k];
        acc += w.x*q.x + w.y*q.y + w.z*q.z + w.w*q.w;
    }
    gt[t] = acc;
    __syncthreads();

    if (t < HH){
        float ig = gt[t], fg = gt[HH+t], gg = gt[2*HH+t], og = gt[3*HH+t];
        float c = sigf(fg)*g_cl[g*HH+t] + sigf(ig)*tanhfast(gg);
        g_cl[g*HH+t] = c;
        g_hl[g*HH+t] = sigf(og)*tanhfast(c);
    }
}

// ---------------- Set2Set attention (one block per graph, 3 in-block passes) ----------------
__global__ __launch_bounds__(256) void k_attn(){
    __shared__ float q[HH];
    __shared__ float red[8];
    __shared__ float rp[8][HH];
    int g = blockIdx.x, t = threadIdx.x, wid = t >> 5, lane = t & 31;
    int s = g_bounds[g], e = g_bounds[g+1];

    if (t < HH){ float qv = g_hl[g*HH + t]; q[t] = qv; g_qs[g*2*HH + t] = qv; }
    __syncthreads();

    const float4* h4 = (const float4*)g_h;
    float4 q4 = ((float4*)q)[lane];

    // pass 1: e[n] = dot(h[n], q), track max
    float lmax = -3.4e38f;
    for (int n = s + wid; n < e; n += 8){
        float4 x4 = h4[n*32 + lane];
        float p = x4.x*q4.x + x4.y*q4.y + x4.z*q4.z + x4.w*q4.w;
#pragma unroll
        for (int o = 16; o; o >>= 1) p += __shfl_xor_sync(0xffffffffu, p, o);
        if (lane == 0) g_e[n] = p;
        lmax = fmaxf(lmax, p);
    }
    if (lane == 0) red[wid] = lmax;
    __syncthreads();
    float emax = -3.4e38f;
#pragma unroll
    for (int w = 0; w < 8; w++) emax = fmaxf(emax, red[w]);
    __syncthreads();

    // pass 2: w = exp(e - emax), sum
    float lsum = 0.f;
    for (int n = s + t; n < e; n += 256){
        float w = __expf(g_e[n] - emax);
        g_e[n] = w;
        lsum += w;
    }
#pragma unroll
    for (int o = 16; o; o >>= 1) lsum += __shfl_xor_sync(0xffffffffu, lsum, o);
    if (lane == 0) red[wid] = lsum;
    __syncthreads();
    float denom = 0.f;
#pragma unroll
    for (int w = 0; w < 8; w++) denom += red[w];

    // pass 3: r = sum_n w[n]*h[n] / denom
    float4 racc = make_float4(0.f,0.f,0.f,0.f);
    for (int n = s + wid; n < e; n += 8){
        float coef = g_e[n];
        float4 x4 = h4[n*32 + lane];
        racc.x += coef*x4.x; racc.y += coef*x4.y;
        racc.z += coef*x4.z; racc.w += coef*x4.w;
    }
    ((float4*)rp[wid])[lane] = racc;
    __syncthreads();
    if (t < HH){
        float r = 0.f;
#pragma unroll
        for (int w = 0; w < 8; w++) r += rp[w][t];
        r = (e > s) ? (r / denom) : 0.f;
        g_qs[g*2*HH + HH + t] = r;
    }
}

// ---------------- prediction ----------------
__global__ __launch_bounds__(128) void k_pred(const float* __restrict__ wp,
                                              const float* __restrict__ bp,
                                              float* __restrict__ out){
    __shared__ float red[4];
    int g = blockIdx.x, t = threadIdx.x;
    float p = g_qs[g*256 + t]*wp[t] + g_qs[g*256 + 128 + t]*wp[128 + t];
#pragma unroll
    for (int o = 16; o; o >>= 1) p += __shfl_xor_sync(0xffffffffu, p, o);
    if ((t & 31) == 0) red[t >> 5] = p;
    __syncthreads();
    if (t == 0) out[g] = red[0] + red[1] + red[2] + red[3] + bp[0];
}

// ---------------- launcher ----------------
extern "C" void kernel_launch(void* const* d_in, const int* in_sizes, int n_in,
                              void* d_out, int out_size){
    const float* x    = (const float*)d_in[0];
    const int*   ei   = (const int*)  d_in[1];
    const int*   batch= (const int*)  d_in[2];
    const float* Win  = (const float*)d_in[3];
    const float* bin  = (const float*)d_in[4];
    const float* Wf   = (const float*)d_in[5];
    const float* Uf   = (const float*)d_in[6];
    const float* bf   = (const float*)d_in[7];
    const float* Wh   = (const float*)d_in[8];
    const float* Uh   = (const float*)d_in[9];
    const float* bh   = (const float*)d_in[10];
    const float* wih  = (const float*)d_in[11];
    const float* whh  = (const float*)d_in[12];
    const float* bih  = (const float*)d_in[13];
    const float* bhh  = (const float*)d_in[14];
    const float* wp   = (const float*)d_in[15];
    const float* bp   = (const float*)d_in[16];
    float* out = (float*)d_out;

    float *p_m, *p_h, *p_fb, *p_gb, *p_Wint, *p_Wft, *p_Uft, *p_Wht, *p_Uht;
    cudaGetSymbolAddress((void**)&p_m,    g_m);
    cudaGetSymbolAddress((void**)&p_h,    g_h);
    cudaGetSymbolAddress((void**)&p_fb,   g_fb);
    cudaGetSymbolAddress((void**)&p_gb,   g_gb);
    cudaGetSymbolAddress((void**)&p_Wint, g_Wint);
    cudaGetSymbolAddress((void**)&p_Wft,  g_Wft);
    cudaGetSymbolAddress((void**)&p_Uft,  g_Uft);
    cudaGetSymbolAddress((void**)&p_Wht,  g_Wht);
    cudaGetSymbolAddress((void**)&p_Uht,  g_Uht);

    cudaFuncSetAttribute(k_dualgemm<0>, cudaFuncAttributeMaxDynamicSharedMemorySize, SMG);
    cudaFuncSetAttribute(k_dualgemm<1>, cudaFuncAttributeMaxDynamicSharedMemorySize, SMG);
    cudaFuncSetAttribute(k_input,       cudaFuncAttributeMaxDynamicSharedMemorySize, 49152);

    dim3 tb(32, 32);
    k_transpose<<<dim3(2,4), tb>>>(Win, p_Wint, 128, 64);
    k_transpose<<<dim3(4,4), tb>>>(Wf,  p_Wft, 128, 128);
    k_transpose<<<dim3(4,4), tb>>>(Uf,  p_Uft, 128, 128);
    k_transpose<<<dim3(4,4), tb>>>(Wh,  p_Wht, 128, 128);
    k_transpose<<<dim3(4,4), tb>>>(Uh,  p_Uht, 128, 128);
    k_bounds<<<(NN+255)/256, 256>>>(batch);
    k_input<<<(NN+63)/64, 256, 49152>>>(x, bin);

    for (int step = 0; step < 3; step++){
        k_zero4<<<(NN*HH/4 + 255)/256, 256>>>((float4*)p_m, NN*HH/4);
        k_scatter<<<(NE*32)/256, 256>>>(ei, ei + NE);
        k_dualgemm<0><<<152, 256, SMG>>>(p_m, p_h,  p_Wft, p_Uft, bf, p_fb, p_gb, nullptr, nullptr);
        k_dualgemm<1><<<152, 256, SMG>>>(p_m, p_gb, p_Wht, p_Uht, bh, nullptr, nullptr, p_fb, p_h);
    }

    k_zero_s2s<<<(NG*2*HH + 255)/256, 256>>>();
    for (int step = 0; step < 3; step++){
        k_lstm<<<NG, 512>>>(wih, whh, bih, bhh);
        k_attn<<<NG, 256>>>();
    }
    k_pred<<<NG, 128>>>(wp, bp, out);
}

// round 4
// speedup vs baseline: 1.2580x; 1.2580x over previous
#include <cuda_runtime.h>
#include <math.h>

#define NN 100000
#define NE 640000
#define IND 64
#define HH  128
#define NG  128

typedef unsigned long long u64;

// ---------------- scratch (static device globals; no runtime alloc) ----------------
__device__ float g_h [NN*HH];
__device__ float g_m [NN*HH];
__device__ float g_fb[NN*HH];
__device__ float g_gb[NN*HH];
__device__ float g_Wint[IND*HH];
__device__ float g_Wft[HH*HH];
__device__ float g_Uft[HH*HH];
__device__ float g_Wht[HH*HH];
__device__ float g_Uht[HH*HH];
__device__ float g_e  [NN];
__device__ int   g_bounds[NG+1];
__device__ float g_hl[NG*HH];
__device__ float g_cl[NG*HH];
__device__ float g_qs[NG*2*HH];

__device__ __forceinline__ float sigf(float z)   { return __fdividef(1.f, 1.f + __expf(-z)); }
__device__ __forceinline__ float tanhfast(float z){ return 1.f - __fdividef(2.f, __expf(2.f*z) + 1.f); }

// ---- packed fp32x2 helpers (sm_103a FFMA2 path, PTX-only) ----
__device__ __forceinline__ u64 dup2(float a){
    u64 r; asm("mov.b64 %0, {%1, %1};" : "=l"(r) : "f"(a)); return r;
}
__device__ __forceinline__ void ffma2(u64& d, u64 a, u64 b){
    asm("fma.rn.f32x2 %0, %1, %2, %0;" : "+l"(d) : "l"(a), "l"(b));
}
__device__ __forceinline__ float2 unpk(u64 v){
    float2 r; asm("mov.b64 {%0, %1}, %2;" : "=f"(r.x), "=f"(r.y) : "l"(v)); return r;
}

// ---------------- transpose: src[R][C] -> dst[C][R] ----------------
__global__ void k_transpose(const float* __restrict__ src, float* __restrict__ dst, int R, int C){
    __shared__ float t[32][33];
    int c = blockIdx.x*32 + threadIdx.x;
    int r = blockIdx.y*32 + threadIdx.y;
    if (r < R && c < C) t[threadIdx.y][threadIdx.x] = src[r*C + c];
    __syncthreads();
    int rc = blockIdx.x*32 + threadIdx.y;
    int cc = blockIdx.y*32 + threadIdx.x;
    if (rc < C && cc < R) dst[rc*R + cc] = t[threadIdx.x][threadIdx.y];
}

// ---------------- segment boundaries from sorted batch ----------------
__global__ void k_bounds(const int* __restrict__ batch){
    int i = blockIdx.x*blockDim.x + threadIdx.x;
    if (i >= NN) return;
    int b = batch[i];
    if (i == 0)      { for (int g = 0;    g <= b;  g++) g_bounds[g] = 0; }
    else             { int pb = batch[i-1];
                       for (int g = pb+1; g <= b;  g++) g_bounds[g] = i; }
    if (i == NN-1)   { for (int g = b+1;  g <= NG; g++) g_bounds[g] = NN; }
}

// ---------------- zero helpers ----------------
__global__ void k_zero4(float4* __restrict__ p, int n4){
    int i = blockIdx.x*blockDim.x + threadIdx.x;
    if (i < n4) p[i] = make_float4(0.f,0.f,0.f,0.f);
}
__global__ void k_zero_s2s(){
    int i = blockIdx.x*blockDim.x + threadIdx.x;
    if (i < NG*HH) { g_hl[i] = 0.f; g_cl[i] = 0.f; }
    if (i < NG*2*HH) g_qs[i] = 0.f;
}

// ---------------- input layer: h = relu(x @ W_in^T + b_in), f32x2 packed ----------------
__global__ __launch_bounds__(256) void k_input(const float* __restrict__ x,
                                               const float* __restrict__ bin){
    extern __shared__ float sm[];
    float4* Ws4 = (float4*)sm;                 // 2048 f4 (k-major Wt: [64][128])
    float4* Xs4 = (float4*)(sm + IND*HH);      // 1024 f4
    int tid = threadIdx.x;
    int jt = tid & 31, nt = tid >> 5;

    const float4* Wg = (const float4*)g_Wint;
#pragma unroll
    for (int i = 0; i < 8; i++) Ws4[tid + i*256] = Wg[tid + i*256];

    int base = blockIdx.x * 64;
    const float4* Xg = (const float4*)x;
#pragma unroll
    for (int i = 0; i < 4; i++){
        int q = tid + i*256;
        int rn = q >> 4, col = q & 15;
        int gn = base + rn;
        Xs4[q] = (gn < NN) ? Xg[gn*16 + col] : make_float4(0.f,0.f,0.f,0.f);
    }
    __syncthreads();

    u64 acc[8][2];
#pragma unroll
    for (int i = 0; i < 8; i++){ acc[i][0] = 0ull; acc[i][1] = 0ull; }

    for (int k = 0; k < IND; k += 4){
        float a[8][4];
#pragma unroll
        for (int i = 0; i < 8; i++){
            float4 t4 = Xs4[(nt*8+i)*16 + (k>>2)];
            a[i][0]=t4.x; a[i][1]=t4.y; a[i][2]=t4.z; a[i][3]=t4.w;
        }
#pragma unroll
        for (int kk = 0; kk < 4; kk++){
            ulonglong2 wv = ((const ulonglong2*)Ws4)[(k+kk)*32 + jt];
#pragma unroll
            for (int i = 0; i < 8; i++){
                u64 a2 = dup2(a[i][kk]);
                ffma2(acc[i][0], a2, wv.x);
                ffma2(acc[i][1], a2, wv.y);
            }
        }
    }
    float4 bb = ((const float4*)bin)[jt];
#pragma unroll
    for (int i = 0; i < 8; i++){
        int n = base + nt*8 + i;
        if (n < NN){
            float2 z01 = unpk(acc[i][0]);
            float2 z23 = unpk(acc[i][1]);
            float4 o;
            o.x = fmaxf(z01.x+bb.x, 0.f);
            o.y = fmaxf(z01.y+bb.y, 0.f);
            o.z = fmaxf(z23.x+bb.z, 0.f);
            o.w = fmaxf(z23.y+bb.w, 0.f);
            ((float4*)g_h)[n*32 + jt] = o;
        }
    }
}

// ---------------- edge scatter: m[dst] += h[src], one warp per edge ----------------
__global__ void k_scatter(const int* __restrict__ src, const int* __restrict__ dst){
    int t = blockIdx.x*blockDim.x + threadIdx.x;
    int e = t >> 5;
    if (e >= NE) return;
    int lane = t & 31;
    int s = __ldg(&src[e]);
    int d = __ldg(&dst[e]);
    float4 v = ((const float4*)g_h)[s*32 + lane];
    float* p = g_m + d*HH + lane*4;
    asm volatile("red.global.add.v4.f32 [%0], {%1, %2, %3, %4};"
                 :: "l"(p), "f"(v.x), "f"(v.y), "f"(v.z), "f"(v.w) : "memory");
}

// ---------------- dual GEMM: z = A@Wt + B@Ut + bias, fused MGU epilogue ----------------
// MODE 0: f = sigmoid(z) -> O1;  g = f * B -> O2
// MODE 1: h_new = (1-Fb)*Hb + Fb*tanh(z) -> Hb (in place)
// persistent grid, 1 block/SM, 192KB dynamic smem, packed f32x2 inner loop
#define SMG ((HH*HH*2 + 64*HH*2) * 4)
template<int MODE>
__global__ __launch_bounds__(256) void k_dualgemm(
    const float* __restrict__ A, const float* __restrict__ B,
    const float* __restrict__ Wt, const float* __restrict__ Ut,
    const float* __restrict__ bias,
    float* __restrict__ O1, float* __restrict__ O2,
    const float* __restrict__ Fb, float* __restrict__ Hb)
{
    extern __shared__ float sm[];
    float4* Ws4 = (float4*)sm;                       // 4096 f4 (k-major)
    float4* Us4 = (float4*)(sm + HH*HH);             // 4096 f4
    float4* As4 = (float4*)(sm + 2*HH*HH);           // 2048 f4
    float4* Bs4 = (float4*)(sm + 2*HH*HH + 64*HH);   // 2048 f4
    int tid = threadIdx.x;
    int jt = tid & 31, nt = tid >> 5;

    const float4* Wg = (const float4*)Wt;
    const float4* Ug = (const float4*)Ut;
#pragma unroll
    for (int i = 0; i < 16; i++){
        Ws4[tid + i*256] = Wg[tid + i*256];
        Us4[tid + i*256] = Ug[tid + i*256];
    }
    float4 bb = ((const float4*)bias)[jt];
    const float4* Ag = (const float4*)A;
    const float4* Bg = (const float4*)B;

    int ntiles = (NN + 63) >> 6;
    for (int tile = blockIdx.x; tile < ntiles; tile += gridDim.x){
        __syncthreads();
        int base = tile << 6;
#pragma unroll
        for (int i = 0; i < 8; i++){
            int q = tid + i*256;
            int rn = q >> 5, col = q & 31;
            int gn = base + rn;
            if (gn < NN){ As4[q] = Ag[gn*32 + col]; Bs4[q] = Bg[gn*32 + col]; }
            else        { float4 z = make_float4(0.f,0.f,0.f,0.f); As4[q] = z; Bs4[q] = z; }
        }
        __syncthreads();

        u64 acc[8][2];
#pragma unroll
        for (int i = 0; i < 8; i++){ acc[i][0] = 0ull; acc[i][1] = 0ull; }

        for (int k = 0; k < HH; k += 4){
            float a[8][4], b[8][4];
#pragma unroll
            for (int i = 0; i < 8; i++){
                float4 ta = As4[(nt*8+i)*32 + (k>>2)];
                float4 tb = Bs4[(nt*8+i)*32 + (k>>2)];
                a[i][0]=ta.x; a[i][1]=ta.y; a[i][2]=ta.z; a[i][3]=ta.w;
                b[i][0]=tb.x; b[i][1]=tb.y; b[i][2]=tb.z; b[i][3]=tb.w;
            }
#pragma unroll
            for (int kk = 0; kk < 4; kk++){
                ulonglong2 wv = ((const ulonglong2*)Ws4)[(k+kk)*32 + jt];
                ulonglong2 uv = ((const ulonglong2*)Us4)[(k+kk)*32 + jt];
#pragma unroll
                for (int i = 0; i < 8; i++){
                    u64 a2 = dup2(a[i][kk]);
                    u64 b2 = dup2(b[i][kk]);
                    ffma2(acc[i][0], a2, wv.x);
                    ffma2(acc[i][1], a2, wv.y);
                    ffma2(acc[i][0], b2, uv.x);
                    ffma2(acc[i][1], b2, uv.y);
                }
            }
        }

#pragma unroll
        for (int i = 0; i < 8; i++){
            int n = base + nt*8 + i;
            if (n < NN){
                float2 z01 = unpk(acc[i][0]);
                float2 z23 = unpk(acc[i][1]);
                float z0 = z01.x+bb.x, z1 = z01.y+bb.y;
                float z2 = z23.x+bb.z, z3 = z23.y+bb.w;
                if (MODE == 0){
                    float f0 = sigf(z0), f1 = sigf(z1), f2 = sigf(z2), f3 = sigf(z3);
                    float4 hv = Bs4[(nt*8+i)*32 + jt];   // h[n][j..j+3]
                    float4 o1 = make_float4(f0, f1, f2, f3);
                    float4 o2 = make_float4(f0*hv.x, f1*hv.y, f2*hv.z, f3*hv.w);
                    ((float4*)O1)[n*32 + jt] = o1;
                    ((float4*)O2)[n*32 + jt] = o2;
                } else {
                    float4 fv = ((const float4*)Fb)[n*32 + jt];
                    float4 hv = ((const float4*)Hb)[n*32 + jt];
                    float4 o;
                    o.x = (1.f-fv.x)*hv.x + fv.x*tanhfast(z0);
                    o.y = (1.f-fv.y)*hv.y + fv.y*tanhfast(z1);
                    o.z = (1.f-fv.z)*hv.z + fv.z*tanhfast(z2);
                    o.w = (1.f-fv.w)*hv.w + fv.w*tanhfast(z3);
                    ((float4*)Hb)[n*32 + jt] = o;
                }
            }
        }
    }
}

// ---------------- Set2Set LSTM step (one block per graph) ----------------
__global__ __launch_bounds__(512) void k_lstm(const float* __restrict__ wih,
                                              const float* __restrict__ whh,
                                              const float* __restrict__ bih,
                                              const float* __restrict__ bhh){
    __shared__ float qs[2*HH];
    __shared__ float hs[HH];
    __shared__ float gt[4*HH];
    int g = blockIdx.x, t = threadIdx.x;
    if (t < 2*HH) qs[t] = g_qs[g*2*HH + t];
    if (t < HH)   hs[t] = g_hl[g*HH + t];
    __syncthreads();

    float acc = bih[t] + bhh[t];
    const float4* wr  = (const float4*)(wih + t*2*HH);
    const float4* qs4 = (const float4*)qs;
#pragma unroll 8
    for (int k = 0; k < 64; k++){
        float4 w = wr[k], q = qs4[k];
        acc += w.x*q.x + w.y*q.y + w.z*q.z + w.w*q.w;
    }
    const float4* hr  = (const float4*)(whh + t*HH);
    const float4* hs4 = (const float4*)hs;
#pragma unroll 8
    for (int k = 0; k < 32; k++){
        float4 w = hr[k], q = hs4[k];
        acc += w.x*q.x + w.y*q.y + w.z*q.z + w.w*q.w;
    }
    gt[t] = acc;
    __syncthreads();

    if (t < HH){
        float ig = gt[t], fg = gt[HH+t], gg = gt[2*HH+t], og = gt[3*HH+t];
        float c = sigf(fg)*g_cl[g*HH+t] + sigf(ig)*tanhfast(gg);
        g_cl[g*HH+t] = c;
        g_hl[g*HH+t] = sigf(og)*tanhfast(c);
    }
}

// ---------------- Set2Set attention (one block per graph, 3 in-block passes) ----------------
__global__ __launch_bounds__(256) void k_attn(){
    __shared__ float q[HH];
    __shared__ float red[8];
    __shared__ float rp[8][HH];
    int g = blockIdx.x, t = threadIdx.x, wid = t >> 5, lane = t & 31;
    int s = g_bounds[g], e = g_bounds[g+1];

    if (t < HH){ float qv = g_hl[g*HH + t]; q[t] = qv; g_qs[g*2*HH + t] = qv; }
    __syncthreads();

    const float4* h4 = (const float4*)g_h;
    float4 q4 = ((float4*)q)[lane];

    float lmax = -3.4e38f;
    for (int n = s + wid; n < e; n += 8){
        float4 x4 = h4[n*32 + lane];
        float p = x4.x*q4.x + x4.y*q4.y + x4.z*q4.z + x4.w*q4.w;
#pragma unroll
        for (int o = 16; o; o >>= 1) p += __shfl_xor_sync(0xffffffffu, p, o);
        if (lane == 0) g_e[n] = p;
        lmax = fmaxf(lmax, p);
    }
    if (lane == 0) red[wid] = lmax;
    __syncthreads();
    float emax = -3.4e38f;
#pragma unroll
    for (int w = 0; w < 8; w++) emax = fmaxf(emax, red[w]);
    __syncthreads();

    float lsum = 0.f;
    for (int n = s + t; n < e; n += 256){
        float w = __expf(g_e[n] - emax);
        g_e[n] = w;
        lsum += w;
    }
#pragma unroll
    for (int o = 16; o; o >>= 1) lsum += __shfl_xor_sync(0xffffffffu, lsum, o);
    if (lane == 0) red[wid] = lsum;
    __syncthreads();
    float denom = 0.f;
#pragma unroll
    for (int w = 0; w < 8; w++) denom += red[w];

    float4 racc = make_float4(0.f,0.f,0.f,0.f);
    for (int n = s + wid; n < e; n += 8){
        float coef = g_e[n];
        float4 x4 = h4[n*32 + lane];
        racc.x += coef*x4.x; racc.y += coef*x4.y;
        racc.z += coef*x4.z; racc.w += coef*x4.w;
    }
    ((float4*)rp[wid])[lane] = racc;
    __syncthreads();
    if (t < HH){
        float r = 0.f;
#pragma unroll
        for (int w = 0; w < 8; w++) r += rp[w][t];
        r = (e > s) ? (r / denom) : 0.f;
        g_qs[g*2*HH + HH + t] = r;
    }
}

// ---------------- prediction ----------------
__global__ __launch_bounds__(128) void k_pred(const float* __restrict__ wp,
                                              const float* __restrict__ bp,
                                              float* __restrict__ out){
    __shared__ float red[4];
    int g = blockIdx.x, t = threadIdx.x;
    float p = g_qs[g*256 + t]*wp[t] + g_qs[g*256 + 128 + t]*wp[128 + t];
#pragma unroll
    for (int o = 16; o; o >>= 1) p += __shfl_xor_sync(0xffffffffu, p, o);
    if ((t & 31) == 0) red[t >> 5] = p;
    __syncthreads();
    if (t == 0) out[g] = red[0] + red[1] + red[2] + red[3] + bp[0];
}

// ---------------- launcher ----------------
extern "C" void kernel_launch(void* const* d_in, const int* in_sizes, int n_in,
                              void* d_out, int out_size){
    const float* x    = (const float*)d_in[0];
    const int*   ei   = (const int*)  d_in[1];
    const int*   batch= (const int*)  d_in[2];
    const float* Win  = (const float*)d_in[3];
    const float* bin  = (const float*)d_in[4];
    const float* Wf   = (const float*)d_in[5];
    const float* Uf   = (const float*)d_in[6];
    const float* bf   = (const float*)d_in[7];
    const float* Wh   = (const float*)d_in[8];
    const float* Uh   = (const float*)d_in[9];
    const float* bh   = (const float*)d_in[10];
    const float* wih  = (const float*)d_in[11];
    const float* whh  = (const float*)d_in[12];
    const float* bih  = (const float*)d_in[13];
    const float* bhh  = (const float*)d_in[14];
    const float* wp   = (const float*)d_in[15];
    const float* bp   = (const float*)d_in[16];
    float* out = (float*)d_out;

    float *p_m, *p_h, *p_fb, *p_gb, *p_Wint, *p_Wft, *p_Uft, *p_Wht, *p_Uht;
    cudaGetSymbolAddress((void**)&p_m,    g_m);
    cudaGetSymbolAddress((void**)&p_h,    g_h);
    cudaGetSymbolAddress((void**)&p_fb,   g_fb);
    cudaGetSymbolAddress((void**)&p_gb,   g_gb);
    cudaGetSymbolAddress((void**)&p_Wint, g_Wint);
    cudaGetSymbolAddress((void**)&p_Wft,  g_Wft);
    cudaGetSymbolAddress((void**)&p_Uft,  g_Uft);
    cudaGetSymbolAddress((void**)&p_Wht,  g_Wht);
    cudaGetSymbolAddress((void**)&p_Uht,  g_Uht);

    cudaFuncSetAttribute(k_dualgemm<0>, cudaFuncAttributeMaxDynamicSharedMemorySize, SMG);
    cudaFuncSetAttribute(k_dualgemm<1>, cudaFuncAttributeMaxDynamicSharedMemorySize, SMG);
    cudaFuncSetAttribute(k_input,       cudaFuncAttributeMaxDynamicSharedMemorySize, 49152);

    dim3 tb(32, 32);
    k_transpose<<<dim3(2,4), tb>>>(Win, p_Wint, 128, 64);
    k_transpose<<<dim3(4,4), tb>>>(Wf,  p_Wft, 128, 128);
    k_transpose<<<dim3(4,4), tb>>>(Uf,  p_Uft, 128, 128);
    k_transpose<<<dim3(4,4), tb>>>(Wh,  p_Wht, 128, 128);
    k_transpose<<<dim3(4,4), tb>>>(Uh,  p_Uht, 128, 128);
    k_bounds<<<(NN+255)/256, 256>>>(batch);
    k_input<<<(NN+63)/64, 256, 49152>>>(x, bin);

    for (int step = 0; step < 3; step++){
        k_zero4<<<(NN*HH/4 + 255)/256, 256>>>((float4*)p_m, NN*HH/4);
        k_scatter<<<(NE*32)/256, 256>>>(ei, ei + NE);
        k_dualgemm<0><<<152, 256, SMG>>>(p_m, p_h,  p_Wft, p_Uft, bf, p_fb, p_gb, nullptr, nullptr);
        k_dualgemm<1><<<152, 256, SMG>>>(p_m, p_gb, p_Wht, p_Uht, bh, nullptr, nullptr, p_fb, p_h);
    }

    k_zero_s2s<<<(NG*2*HH + 255)/256, 256>>>();
    for (int step = 0; step < 3; step++){
        k_lstm<<<NG, 512>>>(wih, whh, bih, bhh);
        k_attn<<<NG, 256>>>();
    }
    k_pred<<<NG, 128>>>(wp, bp, out);
}